// round 2
// baseline (speedup 1.0000x reference)
#include <cuda_runtime.h>
#include <math.h>

// ---------------------------------------------------------------------------
// Seq2Seq LSTM: B=256, T_in=512, F=64, H=512, T_out=64
// Persistent-kernel version: 2 graph nodes total (prep + main) to avoid the
// graph-upload device allocation that a 1226-node graph triggers.
// Inner GEMM: gate-interleaved weights, packed f32x2 FMA, duplicated-A smem,
// double-buffered tiles. Grid barrier between recurrent steps.
// ---------------------------------------------------------------------------

#define Bsz   256
#define Hd    512
#define Fin   64
#define T_IN  512
#define T_OUT 64
#define N4    2048
#define BH    (Bsz*Hd)
#define NBLK  128

#define BM 64
#define BN 64
#define BK 16

// ------------------------- device scratch (static) -------------------------
__device__ float g_hseq[T_IN * BH];
__device__ float g_h1[2][BH];
__device__ float g_hd0[2][BH];
__device__ float g_hd1[2][BH];
__device__ float g_c0[BH];
__device__ float g_c1[BH];
__device__ float g_prev[Bsz];

__device__ float g_Wx0[Fin * N4];
__device__ float g_Wh0[Hd * N4];
__device__ float g_b0[N4];
__device__ float g_Wx1[Hd * N4];
__device__ float g_Wh1[Hd * N4];
__device__ float g_b1[N4];
__device__ float g_Wvd0[N4];
__device__ float g_Whd0[Hd * N4];
__device__ float g_bd0[N4];
__device__ float g_Wxd1[Hd * N4];
__device__ float g_Whd1[Hd * N4];
__device__ float g_bd1[N4];

__device__ unsigned g_cnt;
__device__ volatile unsigned g_gen;

// ------------------------------- helpers -----------------------------------
__device__ __forceinline__ void fma2(unsigned long long& d,
                                     unsigned long long a,
                                     unsigned long long b) {
    asm("fma.rn.f32x2 %0, %1, %2, %0;" : "+l"(d) : "l"(a), "l"(b));
}
__device__ __forceinline__ float2 up2(unsigned long long v) {
    float2 f;
    asm("mov.b64 {%0,%1}, %2;" : "=f"(f.x), "=f"(f.y) : "l"(v));
    return f;
}
__device__ __forceinline__ float sigf(float x) { return 1.0f / (1.0f + expf(-x)); }

__device__ __forceinline__ void grid_sync() {
    __syncthreads();
    if (threadIdx.x == 0) {
        __threadfence();
        unsigned g = g_gen;
        unsigned old = atomicAdd(&g_cnt, 1u);
        if (old == NBLK - 1) {
            g_cnt = 0;
            __threadfence();
            g_gen = g + 1;
        } else {
            while (g_gen == g) __nanosleep(64);
            __threadfence();
        }
    }
    __syncthreads();
}

// --------------------------- fused step GEMM -------------------------------
// acc += A[BM x K] * W[K x 2048] tile (A duplicated in smem for packed f32x2)
__device__ __forceinline__ void gemm_src(
    const float* __restrict__ A, int sa,
    const float* __restrict__ W, int K,
    int bm, int bn, int tid,
    float As2[2][BK][2 * BM], float Bs[2][BK][BN],
    unsigned long long acc[4][2]) {
    const int tx = tid & 15, ty = tid >> 4;
    const int arow = tid >> 2, ak = (tid & 3) << 2;
    const int bk = tid >> 4, bn4 = (tid & 15) << 2;
    const float* aptr = A + (bm + arow) * sa + ak;
    const float* bptr = W + bk * N4 + bn + bn4;
    const int ntile = K >> 4;

    float4 ar = *(const float4*)aptr;
    float4 br = *(const float4*)bptr;

    __syncthreads();   // prior users of smem are done
    {
        *(float2*)&As2[0][ak + 0][2 * arow] = make_float2(ar.x, ar.x);
        *(float2*)&As2[0][ak + 1][2 * arow] = make_float2(ar.y, ar.y);
        *(float2*)&As2[0][ak + 2][2 * arow] = make_float2(ar.z, ar.z);
        *(float2*)&As2[0][ak + 3][2 * arow] = make_float2(ar.w, ar.w);
        *(float4*)&Bs[0][bk][bn4] = br;
    }
    __syncthreads();

    int buf = 0;
    for (int t = 0; t < ntile; ++t) {
        if (t + 1 < ntile) {
            ar = *(const float4*)(aptr + (t + 1) * BK);
            br = *(const float4*)(bptr + (t + 1) * BK * N4);
        }
#pragma unroll
        for (int k = 0; k < BK; ++k) {
            ulonglong2 va = *(const ulonglong2*)&As2[buf][k][ty << 3];
            ulonglong2 vb = *(const ulonglong2*)&As2[buf][k][(ty << 3) + 4];
            ulonglong2 wb = *(const ulonglong2*)&Bs[buf][k][tx << 2];
            fma2(acc[0][0], va.x, wb.x); fma2(acc[0][1], va.x, wb.y);
            fma2(acc[1][0], va.y, wb.x); fma2(acc[1][1], va.y, wb.y);
            fma2(acc[2][0], vb.x, wb.x); fma2(acc[2][1], vb.x, wb.y);
            fma2(acc[3][0], vb.y, wb.x); fma2(acc[3][1], vb.y, wb.y);
        }
        if (t + 1 < ntile) {
            buf ^= 1;
            *(float2*)&As2[buf][ak + 0][2 * arow] = make_float2(ar.x, ar.x);
            *(float2*)&As2[buf][ak + 1][2 * arow] = make_float2(ar.y, ar.y);
            *(float2*)&As2[buf][ak + 2][2 * arow] = make_float2(ar.z, ar.z);
            *(float2*)&As2[buf][ak + 3][2 * arow] = make_float2(ar.w, ar.w);
            *(float4*)&Bs[buf][bk][bn4] = br;
            __syncthreads();
        }
    }
    __syncthreads();   // protect smem for next source
}

// LSTM pointwise epilogue: each thread owns 4 rows x 4 interleaved gate cols
__device__ __forceinline__ void lstm_pointwise(
    unsigned long long acc[4][2],
    const float* __restrict__ bias,
    const float* __restrict__ prev,
    const float* __restrict__ Wvec,
    float* __restrict__ cst,
    float* __restrict__ hnew,
    int bm, int bn, int tid) {
    const int tx = tid & 15, ty = tid >> 4;
    const int n0 = bn + (tx << 2);
    const int j = n0 >> 2;
    const float bi = bias[n0], bf = bias[n0 + 1], bg = bias[n0 + 2], bo = bias[n0 + 3];
    float wv0 = 0.f, wv1 = 0.f, wv2 = 0.f, wv3 = 0.f;
    if (Wvec) { wv0 = Wvec[n0]; wv1 = Wvec[n0 + 1]; wv2 = Wvec[n0 + 2]; wv3 = Wvec[n0 + 3]; }

#pragma unroll
    for (int r = 0; r < 4; ++r) {
        const int b = bm + (ty << 2) + r;
        float2 lo = up2(acc[r][0]);
        float2 hi = up2(acc[r][1]);
        float gi = lo.x + bi, gf = lo.y + bf, gg = hi.x + bg, go = hi.y + bo;
        if (prev) {
            float pv = prev[b];
            gi = fmaf(pv, wv0, gi); gf = fmaf(pv, wv1, gf);
            gg = fmaf(pv, wv2, gg); go = fmaf(pv, wv3, go);
        }
        const int idx = b * Hd + j;
        float cc = cst[idx];
        float cn = sigf(gf) * cc + sigf(gi) * tanhf(gg);
        float hn = sigf(go) * tanhf(cn);
        cst[idx] = cn;
        hnew[idx] = hn;
    }
}

// ------------------------------- prep kernel -------------------------------
// One launch: 5 full reorders, Wx0 reorder, Wvd0, 4 bias combines, zeros, prev
__global__ void prep_kernel(
    const float* __restrict__ x,
    const float* __restrict__ e0Wih, const float* __restrict__ e0Whh,
    const float* __restrict__ e0bih, const float* __restrict__ e0bhh,
    const float* __restrict__ e1Wih, const float* __restrict__ e1Whh,
    const float* __restrict__ e1bih, const float* __restrict__ e1bhh,
    const float* __restrict__ d0Wih, const float* __restrict__ d0Whh,
    const float* __restrict__ d0bih, const float* __restrict__ d0bhh,
    const float* __restrict__ d1Wih, const float* __restrict__ d1Whh,
    const float* __restrict__ d1bih, const float* __restrict__ d1bhh) {
    const int FULL = Hd * N4;          // 1048576
    long long idx = (long long)blockIdx.x * 256 + threadIdx.x;

    // 5 full (K=512) reorders
    if (idx < 5LL * FULL) {
        int seg = (int)(idx / FULL);
        int i = (int)(idx % FULL);
        int k = i % Hd, row = i / Hd;
        int g = row >> 9, j = row & 511;
        int dst = k * N4 + (j << 2) + g;
        const float* src; float* d;
        switch (seg) {
            case 0: src = e0Whh; d = g_Wh0;  break;
            case 1: src = e1Wih; d = g_Wx1;  break;
            case 2: src = e1Whh; d = g_Wh1;  break;
            case 3: src = d0Whh; d = g_Whd0; break;
            default: src = d1Whh; d = g_Whd1; break;
        }
        d[dst] = src[i];
        // seg 4 threads also handle d1Wih (same size)
        if (seg == 4) g_Wxd1[dst] = d1Wih[i];
        return;
    }
    idx -= 5LL * FULL;

    if (idx < Fin * N4) {              // Wx0 reorder (K=64)
        int i = (int)idx;
        int k = i % Fin, row = i / Fin;
        int g = row >> 9, j = row & 511;
        g_Wx0[k * N4 + (j << 2) + g] = e0Wih[i];
        return;
    }
    idx -= Fin * N4;

    if (idx < N4) {                    // Wvd0 (K=1) + all 4 combined biases
        int row = (int)idx;
        int g = row >> 9, j = row & 511;
        int dst = (j << 2) + g;
        g_Wvd0[dst] = d0Wih[row];
        g_b0[dst]  = e0bih[row] + e0bhh[row];
        g_b1[dst]  = e1bih[row] + e1bhh[row];
        g_bd0[dst] = d0bih[row] + d0bhh[row];
        g_bd1[dst] = d1bih[row] + d1bhh[row];
        return;
    }
    idx -= N4;

    if (idx < BH) {                    // zero c0, c1
        g_c0[idx] = 0.0f;
        g_c1[idx] = 0.0f;
        return;
    }
    idx -= BH;

    if (idx < Bsz) {                   // prev = x[:, -1, -1]
        g_prev[idx] = x[idx * T_IN * Fin + (T_IN - 1) * Fin + (Fin - 1)];
        return;
    }
    idx -= Bsz;

    if (idx == 0) { g_cnt = 0; }       // barrier state reset
}

// ------------------------------ main kernel --------------------------------
__global__ void __launch_bounds__(256, 1) main_kernel(
    const float* __restrict__ x,
    const float* __restrict__ projW,
    const float* __restrict__ projb,
    float* __restrict__ out) {
    __shared__ __align__(16) float As2[2][BK][2 * BM];
    __shared__ __align__(16) float Bs[2][BK][BN];
    __shared__ float red[8];

    const int tid = threadIdx.x;
    const int bid = blockIdx.x;
    const int bm = (bid >> 5) * BM;
    const int bn = (bid & 31) * BN;

    unsigned long long acc[4][2];

    // ---------------- encoder layer 0 ----------------
    for (int t = 0; t < T_IN; ++t) {
#pragma unroll
        for (int r = 0; r < 4; ++r) { acc[r][0] = 0ull; acc[r][1] = 0ull; }
        gemm_src(x + t * Fin, T_IN * Fin, g_Wx0, Fin, bm, bn, tid, As2, Bs, acc);
        if (t)
            gemm_src(g_hseq + (t - 1) * BH, Hd, g_Wh0, Hd, bm, bn, tid, As2, Bs, acc);
        lstm_pointwise(acc, g_b0, nullptr, nullptr, g_c0, g_hseq + t * BH, bm, bn, tid);
        grid_sync();
    }

    // ---------------- encoder layer 1 ----------------
    for (int t = 0; t < T_IN; ++t) {
#pragma unroll
        for (int r = 0; r < 4; ++r) { acc[r][0] = 0ull; acc[r][1] = 0ull; }
        gemm_src(g_hseq + t * BH, Hd, g_Wx1, Hd, bm, bn, tid, As2, Bs, acc);
        if (t)
            gemm_src(&g_h1[(t + 1) & 1][0], Hd, g_Wh1, Hd, bm, bn, tid, As2, Bs, acc);
        lstm_pointwise(acc, g_b1, nullptr, nullptr, g_c1, &g_h1[t & 1][0], bm, bn, tid);
        grid_sync();
    }

    // ---------------- decoder ----------------
    const float* h0p = g_hseq + (T_IN - 1) * BH;
    const float* h1p = &g_h1[(T_IN - 1) & 1][0];
    for (int t = 0; t < T_OUT; ++t) {
        // layer 0: K = Hd (hidden) + scalar prev handled in epilogue
#pragma unroll
        for (int r = 0; r < 4; ++r) { acc[r][0] = 0ull; acc[r][1] = 0ull; }
        gemm_src(h0p, Hd, g_Whd0, Hd, bm, bn, tid, As2, Bs, acc);
        lstm_pointwise(acc, g_bd0, g_prev, g_Wvd0, g_c0, &g_hd0[t & 1][0], bm, bn, tid);
        grid_sync();

        // layer 1
#pragma unroll
        for (int r = 0; r < 4; ++r) { acc[r][0] = 0ull; acc[r][1] = 0ull; }
        gemm_src(&g_hd0[t & 1][0], Hd, g_Wxd1, Hd, bm, bn, tid, As2, Bs, acc);
        gemm_src(h1p, Hd, g_Whd1, Hd, bm, bn, tid, As2, Bs, acc);
        lstm_pointwise(acc, g_bd1, nullptr, nullptr, g_c1, &g_hd1[t & 1][0], bm, bn, tid);
        grid_sync();

        // projection: each CTA does 2 batch rows (128 threads each)
        {
            const int b = bid * 2 + (tid >> 7);
            const int lane = tid & 127;
            const float* h = &g_hd1[t & 1][0] + b * Hd;
            float s = 0.f;
            for (int k = lane; k < Hd; k += 128) s += h[k] * projW[k];
#pragma unroll
            for (int off = 16; off > 0; off >>= 1)
                s += __shfl_xor_sync(0xffffffffu, s, off);
            if ((tid & 31) == 0) red[tid >> 5] = s;
            __syncthreads();
            if (lane == 0) {
                const int w0 = (tid >> 7) * 4;
                float v = red[w0] + red[w0 + 1] + red[w0 + 2] + red[w0 + 3] + projb[0];
                out[b * T_OUT + t] = v;
                g_prev[b] = v;
            }
        }
        grid_sync();

        h0p = &g_hd0[t & 1][0];
        h1p = &g_hd1[t & 1][0];
    }
}

// ------------------------------- host side ---------------------------------
extern "C" void kernel_launch(void* const* d_in, const int* in_sizes, int n_in,
                              void* d_out, int out_size) {
    const float* x      = (const float*)d_in[0];
    const float* e0Wih  = (const float*)d_in[2];
    const float* e0Whh  = (const float*)d_in[3];
    const float* e0bih  = (const float*)d_in[4];
    const float* e0bhh  = (const float*)d_in[5];
    const float* e1Wih  = (const float*)d_in[6];
    const float* e1Whh  = (const float*)d_in[7];
    const float* e1bih  = (const float*)d_in[8];
    const float* e1bhh  = (const float*)d_in[9];
    const float* d0Wih  = (const float*)d_in[10];
    const float* d0Whh  = (const float*)d_in[11];
    const float* d0bih  = (const float*)d_in[12];
    const float* d0bhh  = (const float*)d_in[13];
    const float* d1Wih  = (const float*)d_in[14];
    const float* d1Whh  = (const float*)d_in[15];
    const float* d1bih  = (const float*)d_in[16];
    const float* d1bhh  = (const float*)d_in[17];
    const float* projW  = (const float*)d_in[18];
    const float* projb  = (const float*)d_in[19];
    float* out = (float*)d_out;

    // prep: total work items = 5*512*2048 + 64*2048 + 2048 + 131072 + 256 + 1
    const long long total = 5LL * Hd * N4 + (long long)Fin * N4 + N4 + BH + Bsz + 1;
    const int nblk = (int)((total + 255) / 256);
    prep_kernel<<<nblk, 256>>>(x,
        e0Wih, e0Whh, e0bih, e0bhh,
        e1Wih, e1Whh, e1bih, e1bhh,
        d0Wih, d0Whh, d0bih, d0bhh,
        d1Wih, d1Whh, d1bih, d1bhh);

    main_kernel<<<NBLK, 256>>>(x, projW, projb, out);
}